// round 15
// baseline (speedup 1.0000x reference)
#include <cuda_runtime.h>
#include <cuda_bf16.h>
#include <math.h>

// ---------------------------------------------------------------------------
// PositionalEmbedding: out[n, d] = (x[n]==0 ? 0 : W[x[n], d]) + PE(n+1, d)
// N=131072, D=1024, V=50257, fp32. HBM-bound.
// R1:  194us @ 64% DRAM (MLP=1).
// R5:  145.5us kernel @ 78.3% DRAM (ROWS=4 + __stcs).
// R10: ROWS=8 regs48 occ55 REGRESSED; evict_last neutral (traffic flat).
// R12: prefetch.global.L2 for rows 4-7: 142.3us @ 81.1% DRAM -- but regs
//      stayed 48 (idx[4..7] live across half A) -> occ 51.6%.
// R13-R15: shrink live ranges (re-load idx for half B from L1) +
//      __launch_bounds__(256,6) to force <=42 regs -> occ ~75%.
//      (R13/R14 benches were infra failures; re-landing unchanged.)
// ---------------------------------------------------------------------------

#define MAX_D 4096
__device__ float g_wtab[MAX_D];

// w[j] = fp32( pow( (double)fp32(1e-4), expo_j ) ) -- matches reference's
// fp32 pow bits (correctly rounded pow of the fp32-rounded base).
__global__ void build_wtab_kernel(int D) {
    int j = blockIdx.x * blockDim.x + threadIdx.x;
    if (j >= D) return;
    float jf = (float)j;
    float Df = (float)D;
    float e = (j & 1) ? (jf + 1.0f) / Df : jf / Df;   // exact (D = 2^k)
    const double B = (double)(1.0f / 10000.0f);
    g_wtab[j] = (float)pow(B, (double)e);
}

// 3-term FMA Cody-Waite reduction mod 2*pi. ang <= ~131072 -> q < 2^15;
// C1 has 8 mantissa bits so q*C1 exact; total reduction err ~5e-7 abs.
__device__ __forceinline__ float reduce_2pi(float ang) {
    const float INV2PI = 0.15915494309189535f;
    constexpr double TWO_PI = 6.28318530717958647692528676655900577;
    constexpr float C1 = 6.28125f;
    constexpr float C2 = (float)(TWO_PI - (double)C1);
    constexpr float C3 = (float)(TWO_PI - (double)C1 - (double)((float)(TWO_PI - (double)C1)));
    float q = rintf(__fmul_rn(ang, INV2PI));
    float r = __fmaf_rn(-q, C1, ang);
    r = __fmaf_rn(-q, C2, r);
    r = __fmaf_rn(-q, C3, r);
    return r;
}

__device__ __forceinline__ float pe_cos(float posf, float w) {
    return __cosf(reduce_2pi(__fmul_rn(posf, w)));    // MUFU.COS
}
__device__ __forceinline__ float pe_sin(float posf, float w) {
    return __sinf(reduce_2pi(__fmul_rn(posf, w)));    // MUFU.SIN
}

__device__ __forceinline__ void prefetch_l2(const void* p) {
    asm volatile("prefetch.global.L2 [%0];" :: "l"(p));
}

#define ROWS 8      // rows per block: 4 gathered + 4 L2-prefetched, then swap

__global__ void __launch_bounds__(256, 6) pos_emb_kernel(
    const int* __restrict__ x,
    const float* __restrict__ W,
    float* __restrict__ out,
    int D4, int N)
{
    int t = threadIdx.x;
    if (t >= D4) return;
    int row0 = blockIdx.x * ROWS;       // multiple of 8 -> 16B-aligned idx loads
    bool full = (row0 + ROWS <= N);

    const float4* wt4 = reinterpret_cast<const float4*>(g_wtab);
    float4 w4 = wt4[t];                 // 4 KB table, L1-resident
    const float4* Wv = reinterpret_cast<const float4*>(W);
    float4* out4 = reinterpret_cast<float4*>(out);

    // --- Front window -----------------------------------------------------
    // idx[0..3] gathered now; idx[4..7] only used to FORM PREFETCH ADDRESSES,
    // then dropped (re-loaded later from L1) to keep live ranges short.
    int idxA[4];
    float4 e[4];
    if (full) {
        int4 iA = __ldg(reinterpret_cast<const int4*>(x + row0));
        idxA[0] = iA.x; idxA[1] = iA.y; idxA[2] = iA.z; idxA[3] = iA.w;
#pragma unroll
        for (int r = 0; r < 4; r++)
            e[r] = __ldg(Wv + (size_t)idxA[r] * (size_t)D4 + t);
        if ((t & 7) == 0) {             // 1 lane per 128B line -> 4 reqs/warp
            int4 iB = __ldg(reinterpret_cast<const int4*>(x + row0 + 4));
            prefetch_l2(Wv + (size_t)iB.x * (size_t)D4 + t);
            prefetch_l2(Wv + (size_t)iB.y * (size_t)D4 + t);
            prefetch_l2(Wv + (size_t)iB.z * (size_t)D4 + t);
            prefetch_l2(Wv + (size_t)iB.w * (size_t)D4 + t);
        }
    } else {
#pragma unroll
        for (int r = 0; r < 4; r++) {
            int row = row0 + r;
            idxA[r] = (row < N) ? __ldg(x + row) : 0;
            e[r] = __ldg(Wv + (size_t)idxA[r] * (size_t)D4 + t);
        }
    }

    // --- Half A: compute + streaming-store rows 0-3 -----------------------
#pragma unroll
    for (int r = 0; r < 4; r++) {
        int row = row0 + r;
        if (row >= N) break;
        float posf = (float)(row + 1);
        float4 v = (idxA[r] != 0) ? e[r] : make_float4(0.f, 0.f, 0.f, 0.f);
        float4 o;
        o.x = v.x + pe_cos(posf, w4.x); // j even -> cos, j odd -> sin
        o.y = v.y + pe_sin(posf, w4.y);
        o.z = v.z + pe_cos(posf, w4.z);
        o.w = v.w + pe_sin(posf, w4.w);
        __stcs(out4 + (size_t)row * (size_t)D4 + t, o);
    }

    // --- Half B: re-load indices (L1 hit), gathers land in L2 -------------
    int idxB[4];
    if (full) {
        int4 iB = __ldg(reinterpret_cast<const int4*>(x + row0 + 4));
        idxB[0] = iB.x; idxB[1] = iB.y; idxB[2] = iB.z; idxB[3] = iB.w;
    } else {
#pragma unroll
        for (int r = 0; r < 4; r++) {
            int row = row0 + 4 + r;
            idxB[r] = (row < N) ? __ldg(x + row) : 0;
        }
    }
#pragma unroll
    for (int r = 0; r < 4; r++)
        e[r] = __ldg(Wv + (size_t)idxB[r] * (size_t)D4 + t);

#pragma unroll
    for (int r = 0; r < 4; r++) {
        int row = row0 + 4 + r;
        if (row >= N) break;
        float posf = (float)(row + 1);
        float4 v = (idxB[r] != 0) ? e[r] : make_float4(0.f, 0.f, 0.f, 0.f);
        float4 o;
        o.x = v.x + pe_cos(posf, w4.x);
        o.y = v.y + pe_sin(posf, w4.y);
        o.z = v.z + pe_cos(posf, w4.z);
        o.w = v.w + pe_sin(posf, w4.w);
        __stcs(out4 + (size_t)row * (size_t)D4 + t, o);
    }
}

extern "C" void kernel_launch(void* const* d_in, const int* in_sizes, int n_in,
                              void* d_out, int out_size) {
    int xi = 0, wi = 1;
    if (n_in >= 2 && in_sizes[0] > in_sizes[1]) { xi = 1; wi = 0; }
    const int*   x = (const int*)d_in[xi];
    const float* W = (const float*)d_in[wi];
    float* out = (float*)d_out;

    int N = in_sizes[xi];
    int D = out_size / N;               // 1024
    if (D > MAX_D) D = MAX_D;
    int D4 = D / 4;

    build_wtab_kernel<<<(D + 255) / 256, 256>>>(D);
    int nblk = (N + ROWS - 1) / ROWS;
    pos_emb_kernel<<<nblk, D4>>>(x, W, out, D4, N);
}